// round 8
// baseline (speedup 1.0000x reference)
#include <cuda_runtime.h>
#include <math.h>

#define HID   2048
#define MROWS 2048      // b*s = 2*1024
#define SEQ   1024
#define NHEADS 32
#define NKV   8
#define HD    64
#define FFND  8192

// ---------------- scratch (static device arrays; no allocation) ----------------
__device__ float d_normed [MROWS * HID];
__device__ float d_q      [MROWS * HID];
__device__ float d_k      [MROWS * NKV * HD];
__device__ float d_v      [MROWS * NKV * HD];
__device__ float d_ctx    [MROWS * HID];
__device__ float d_attn   [MROWS * HID];
__device__ float d_normed2[MROWS * HID];
__device__ float d_g      [MROWS * FFND];
__device__ float d_u      [MROWS * FFND];
__device__ float d_rope   [MROWS * 64];       // per-row cos[32] | sin[32]

// ---------------- helpers ----------------
__device__ __forceinline__ unsigned f2tf(float x) {
    unsigned u;
    asm("cvt.rna.tf32.f32 %0, %1;" : "=r"(u) : "f"(x));
    return u;
}

// ---------------- RMSNorm (optional fused residual add on the input) ----------------
__global__ void __launch_bounds__(256) rmsnorm_kernel(
    const float* __restrict__ x, const float* __restrict__ res,
    const float* __restrict__ w, float* __restrict__ out)
{
    int row = blockIdx.x;
    int tid = threadIdx.x;
    const float4* xr = reinterpret_cast<const float4*>(x + (size_t)row * HID);
    float4 v0 = xr[tid];
    float4 v1 = xr[tid + 256];
    if (res) {
        const float4* rr = reinterpret_cast<const float4*>(res + (size_t)row * HID);
        float4 r0 = rr[tid], r1 = rr[tid + 256];
        v0.x += r0.x; v0.y += r0.y; v0.z += r0.z; v0.w += r0.w;
        v1.x += r1.x; v1.y += r1.y; v1.z += r1.z; v1.w += r1.w;
    }
    float ss = v0.x*v0.x + v0.y*v0.y + v0.z*v0.z + v0.w*v0.w
             + v1.x*v1.x + v1.y*v1.y + v1.z*v1.z + v1.w*v1.w;
    #pragma unroll
    for (int o = 16; o; o >>= 1) ss += __shfl_xor_sync(0xffffffffu, ss, o);
    __shared__ float red[8];
    if ((tid & 31) == 0) red[tid >> 5] = ss;
    __syncthreads();
    float tot = red[0] + red[1] + red[2] + red[3] + red[4] + red[5] + red[6] + red[7];
    float sc = rsqrtf(tot / (float)HID + 1e-5f);
    const float4* wr = reinterpret_cast<const float4*>(w);
    float4 w0 = wr[tid], w1 = wr[tid + 256];
    float4 o0 = make_float4(v0.x*sc*w0.x, v0.y*sc*w0.y, v0.z*sc*w0.z, v0.w*sc*w0.w);
    float4 o1 = make_float4(v1.x*sc*w1.x, v1.y*sc*w1.y, v1.z*sc*w1.z, v1.w*sc*w1.w);
    float4* orow = reinterpret_cast<float4*>(out + (size_t)row * HID);
    orow[tid]       = o0;
    orow[tid + 256] = o1;
}

// ---------------- tf32 GEMM core: 128x128 tile, BK=16, 3-stage cp.async pipeline ----
// ONE __syncthreads per K-tile (3 stages make the single-barrier scheme sound:
// the write target of iteration kt was last read in kt-1, proven done by kt's barrier).
// MODE: 0 = plain, 1 = C = acc + Add, 2 = C = silu(acc) * Add   (swiglu fusion)
#define STG_FLOATS (128 * 20 + 16 * 136)             // 4736 floats per stage
#define GEMM_SMEM  (3 * STG_FLOATS * 4)              // 56832 bytes

template<int MODE>
__device__ __forceinline__ void gemm_body(
    const float* __restrict__ A, const float* __restrict__ B,
    float* __restrict__ C, const float* __restrict__ Add,
    int N, int K, int bm, int bn)
{
    constexpr int BK = 16;
    extern __shared__ float smg[];
    // stage s: As at smg + s*STG_FLOATS (128x20, pad->frag banks (20g+t)%32 distinct)
    //          Bs at smg + s*STG_FLOATS + 2560 (16x136, pad->banks (8t+g)%32 distinct)

    int tid = threadIdx.x;
    int warp = tid >> 5, lane = tid & 31;
    int wm = (warp >> 2) * 64, wn = (warp & 3) * 32;
    int g = lane >> 2, t = lane & 3;

    int ar0 = tid >> 2, ac0 = (tid & 3) * 4;   // A: 16B chunk coords
    int br0 = tid >> 5, bc0 = (tid & 31) * 4;  // B: 16B chunk coords

    const float* aSrc = A + (size_t)(bm + ar0) * K + ac0;
    const float* bSrc = B + (size_t)br0 * N + bn + bc0;
    const size_t aStep = 64 * (size_t)K;
    const size_t bStep = 8 * (size_t)N;

    float acc[4][4][4] = {};
    int KT = K >> 4;

    auto issue = [&](int buf) {
        float* As = smg + buf * STG_FLOATS;
        float* Bs = As + 2560;
        unsigned d0 = (unsigned)__cvta_generic_to_shared(As + ar0 * 20 + ac0);
        asm volatile("cp.async.cg.shared.global [%0], [%1], 16;\n" :: "r"(d0), "l"(aSrc));
        unsigned d1 = (unsigned)__cvta_generic_to_shared(As + (ar0 + 64) * 20 + ac0);
        asm volatile("cp.async.cg.shared.global [%0], [%1], 16;\n" :: "r"(d1), "l"(aSrc + aStep));
        unsigned d2 = (unsigned)__cvta_generic_to_shared(Bs + br0 * 136 + bc0);
        asm volatile("cp.async.cg.shared.global [%0], [%1], 16;\n" :: "r"(d2), "l"(bSrc));
        unsigned d3 = (unsigned)__cvta_generic_to_shared(Bs + (br0 + 8) * 136 + bc0);
        asm volatile("cp.async.cg.shared.global [%0], [%1], 16;\n" :: "r"(d3), "l"(bSrc + bStep));
        asm volatile("cp.async.commit_group;\n");
        aSrc += BK;
        bSrc += (size_t)BK * N;
    };

    issue(0);
    if (KT > 1) issue(1);

    for (int kt = 0; kt < KT; kt++) {
        if (kt + 1 < KT) {
            asm volatile("cp.async.wait_group 1;\n");   // tile kt arrived, kt+1 may fly
        } else {
            asm volatile("cp.async.wait_group 0;\n");   // last tile: drain all
        }
        __syncthreads();                                 // single barrier per tile

        if (kt + 2 < KT) issue((kt + 2) % 3);            // overlap copy with compute

        const float* As = smg + (kt % 3) * STG_FLOATS;
        const float* Bs = As + 2560;

        #pragma unroll
        for (int ks = 0; ks < BK; ks += 8) {
            unsigned a[4][4], b[4][2];
            #pragma unroll
            for (int mi = 0; mi < 4; mi++) {
                int r = wm + mi * 16 + g;
                a[mi][0] = f2tf(As[ r      * 20 + ks + t]);
                a[mi][1] = f2tf(As[(r + 8) * 20 + ks + t]);
                a[mi][2] = f2tf(As[ r      * 20 + ks + t + 4]);
                a[mi][3] = f2tf(As[(r + 8) * 20 + ks + t + 4]);
            }
            #pragma unroll
            for (int ni = 0; ni < 4; ni++) {
                int c = wn + ni * 8 + g;
                b[ni][0] = f2tf(Bs[(ks + t    ) * 136 + c]);
                b[ni][1] = f2tf(Bs[(ks + t + 4) * 136 + c]);
            }
            #pragma unroll
            for (int mi = 0; mi < 4; mi++)
                #pragma unroll
                for (int ni = 0; ni < 4; ni++) {
                    asm volatile(
                        "mma.sync.aligned.m16n8k8.row.col.f32.tf32.tf32.f32 "
                        "{%0,%1,%2,%3},{%4,%5,%6,%7},{%8,%9},{%0,%1,%2,%3};"
                        : "+f"(acc[mi][ni][0]), "+f"(acc[mi][ni][1]),
                          "+f"(acc[mi][ni][2]), "+f"(acc[mi][ni][3])
                        : "r"(a[mi][0]), "r"(a[mi][1]), "r"(a[mi][2]), "r"(a[mi][3]),
                          "r"(b[ni][0]), "r"(b[ni][1]));
                }
        }
    }

    // epilogue (float2 stores)
    #pragma unroll
    for (int mi = 0; mi < 4; mi++) {
        #pragma unroll
        for (int ni = 0; ni < 4; ni++) {
            int r0 = bm + wm + mi * 16 + g;
            int c0 = bn + wn + ni * 8 + 2 * t;
            size_t i0 = (size_t)r0 * N + c0;
            size_t i1 = i0 + (size_t)8 * N;
            float2 lo = make_float2(acc[mi][ni][0], acc[mi][ni][1]);
            float2 hi = make_float2(acc[mi][ni][2], acc[mi][ni][3]);
            if (MODE == 1) {
                const float2 a0 = *reinterpret_cast<const float2*>(Add + i0);
                const float2 a1 = *reinterpret_cast<const float2*>(Add + i1);
                lo.x += a0.x; lo.y += a0.y; hi.x += a1.x; hi.y += a1.y;
            } else if (MODE == 2) {
                const float2 a0 = *reinterpret_cast<const float2*>(Add + i0);
                const float2 a1 = *reinterpret_cast<const float2*>(Add + i1);
                lo.x = lo.x / (1.f + __expf(-lo.x)) * a0.x;
                lo.y = lo.y / (1.f + __expf(-lo.y)) * a0.y;
                hi.x = hi.x / (1.f + __expf(-hi.x)) * a1.x;
                hi.y = hi.y / (1.f + __expf(-hi.y)) * a1.y;
            }
            *reinterpret_cast<float2*>(C + i0) = lo;
            *reinterpret_cast<float2*>(C + i1) = hi;
        }
    }
}

template<int MODE>
__global__ void __launch_bounds__(256, 2) gemm_tf32(
    const float* __restrict__ A, const float* __restrict__ B,
    float* __restrict__ C, const float* __restrict__ Add,
    int N, int K)
{
    gemm_body<MODE>(A, B, C, Add, N, K, blockIdx.y * 128, blockIdx.x * 128);
}

// fused QKV: grid (24, 16); tiles 0-15 -> Q, 16-19 -> K, 20-23 -> V
__global__ void __launch_bounds__(256, 2) qkv_kernel(
    const float* __restrict__ A,
    const float* __restrict__ wq, const float* __restrict__ wk, const float* __restrict__ wv,
    float* __restrict__ q, float* __restrict__ k, float* __restrict__ v)
{
    int nt = blockIdx.x, bm = blockIdx.y * 128;
    const float* B; float* Cp; int N, bn;
    if (nt < 16)      { B = wq; Cp = q; N = HID;      bn = nt * 128; }
    else if (nt < 20) { B = wk; Cp = k; N = NKV * HD; bn = (nt - 16) * 128; }
    else              { B = wv; Cp = v; N = NKV * HD; bn = (nt - 20) * 128; }
    gemm_body<0>(A, B, Cp, nullptr, N, HID, bm, bn);
}

// ---------------- RoPE: per-row cos/sin table, then memory-bound apply ----------------
__global__ void __launch_bounds__(256) rope_table(
    const int* __restrict__ pos, float* __restrict__ tab)
{
    int idx = blockIdx.x * 256 + threadIdx.x;   // MROWS*32
    int row = idx >> 5, i = idx & 31;
    double invf = exp2(-(double)i * (18.931568569324174 / 32.0)); // 500000^{-i/32}
    float ang = (float)((double)pos[row] * invf);
    float s, c;
    sincosf(ang, &s, &c);
    tab[row * 64 + i]      = c;
    tab[row * 64 + 32 + i] = s;
}

__global__ void __launch_bounds__(256) rope_apply(
    float* __restrict__ q, float* __restrict__ k, const float* __restrict__ tab)
{
    int id = blockIdx.x * 256 + threadIdx.x;    // MROWS * 40 * 32
    int row = id / (40 * 32);
    int rem = id - row * (40 * 32);
    int head = rem >> 5;
    int i = rem & 31;
    float c = tab[row * 64 + i], s = tab[row * 64 + 32 + i];
    float* base;
    if (head < NHEADS) base = q + (size_t)row * HID + head * HD;
    else               base = k + (size_t)row * (NKV * HD) + (head - NHEADS) * HD;
    float x1 = base[i], x2 = base[i + 32];
    base[i]      = x1 * c - x2 * s;
    base[i + 32] = x2 * c + x1 * s;
}

// ---------------- tensor-core flash attention (tf32 mma, causal, GQA) ----------------
// Block: 128 q-rows x one head. 8 warps; warp w owns q-rows [16w, 16w+16) x ALL 64 key
// cols (ni=0..7) so online-softmax row state is warp-private. Key tiles of 64.
#define APAD 68
#define ATTM_SMEM ((128 + 64 + 128 + 64) * APAD * 4)
__global__ void __launch_bounds__(256) attn_mma(
    const float* __restrict__ q, const float* __restrict__ kk,
    const float* __restrict__ vv, float* __restrict__ ctx)
{
    extern __shared__ float sm[];
    float* Qs = sm;                   // [128][APAD] q rows (pre-scaled by 1/8)
    float* Ks = Qs + 128 * APAD;      // [64][APAD]  key rows
    float* Ps = Ks + 64 * APAD;       // [128][APAD] probabilities (warp-private rows)
    float* Vt = Ps + 128 * APAD;      // [64][APAD]  V transposed: Vt[d][kc]

    int qt = blockIdx.x, bh = blockIdx.y;
    int b = bh >> 5, h = bh & 31, kvh = h >> 2;
    const float* qb = q  + ((size_t)b * SEQ + qt * 128) * HID + h * HD;
    const float* kb = kk + (size_t)b * SEQ * (NKV * HD) + kvh * HD;
    const float* vb = vv + (size_t)b * SEQ * (NKV * HD) + kvh * HD;

    int tid = threadIdx.x, warp = tid >> 5, lane = tid & 31;
    int wm = warp * 16;
    int g = lane >> 2, t = lane & 3;

    // load Q tile (128x64), pre-scaled by 0.125 (exact power of two)
    #pragma unroll
    for (int i = 0; i < 8; i++) {
        int idx = tid + i * 256;
        int r = idx >> 4, c4 = idx & 15;
        float4 val = *reinterpret_cast<const float4*>(qb + (size_t)r * HID + c4 * 4);
        val.x *= 0.125f; val.y *= 0.125f; val.z *= 0.125f; val.w *= 0.125f;
        *reinterpret_cast<float4*>(Qs + r * APAD + c4 * 4) = val;
    }

    float acc_o[8][4] = {};
    float m_[2] = {-1e30f, -1e30f};
    float l_[2] = {0.f, 0.f};

    int ktmax = 2 * qt + 1;
    for (int kt = 0; kt <= ktmax; kt++) {
        // load K rows + V transposed (64x64 each)
        #pragma unroll
        for (int i = 0; i < 4; i++) {
            int idx = tid + i * 256;
            int r = idx >> 4, c4 = idx & 15;
            float4 kval = *reinterpret_cast<const float4*>(kb + (size_t)(kt * 64 + r) * (NKV * HD) + c4 * 4);
            *reinterpret_cast<float4*>(Ks + r * APAD + c4 * 4) = kval;
            float4 vval = *reinterpret_cast<const float4*>(vb + (size_t)(kt * 64 + r) * (NKV * HD) + c4 * 4);
            Vt[(c4 * 4 + 0) * APAD + r] = vval.x;
            Vt[(c4 * 4 + 1) * APAD + r] = vval.y;
            Vt[(c4 * 4 + 2) * APAD + r] = vval.z;
            Vt[(c4 * 4 + 3) * APAD + r] = vval.w;
        }
        __syncthreads();

        // S = Qs @ K^T  : warp computes its 16 rows x all 64 cols
        float s[8][4] = {};
        #pragma unroll
        for (int k8 = 0; k8 < 64; k8 += 8) {
            unsigned a[4];
            int r = wm + g;
            a[0] = f2tf(Qs[ r      * APAD + k8 + t]);
            a[1] = f2tf(Qs[(r + 8) * APAD + k8 + t]);
            a[2] = f2tf(Qs[ r      * APAD + k8 + t + 4]);
            a[3] = f2tf(Qs[(r + 8) * APAD + k8 + t + 4]);
            #pragma unroll
            for (int ni = 0; ni < 8; ni++) {
                int c = ni * 8 + g;
                unsigned b0 = f2tf(Ks[c * APAD + k8 + t]);
                unsigned b1 = f2tf(Ks[c * APAD + k8 + t + 4]);
                asm volatile(
                    "mma.sync.aligned.m16n8k8.row.col.f32.tf32.tf32.f32 "
                    "{%0,%1,%2,%3},{%4,%5,%6,%7},{%8,%9},{%0,%1,%2,%3};"
                    : "+f"(s[ni][0]), "+f"(s[ni][1]), "+f"(s[ni][2]), "+f"(s[ni][3])
                    : "r"(a[0]), "r"(a[1]), "r"(a[2]), "r"(a[3]), "r"(b0), "r"(b1));
            }
        }

        // causal mask (only the two diagonal-straddling key tiles can mask)
        if (kt >= 2 * qt) {
            int R0 = qt * 128 + wm + g, R1 = R0 + 8;
            #pragma unroll
            for (int ni = 0; ni < 8; ni++) {
                int c0 = kt * 64 + ni * 8 + 2 * t;
                if (c0     > R0) s[ni][0] = -1e30f;
                if (c0 + 1 > R0) s[ni][1] = -1e30f;
                if (c0     > R1) s[ni][2] = -1e30f;
                if (c0 + 1 > R1) s[ni][3] = -1e30f;
            }
        }

        // online softmax: rows fully warp-owned; reduce over 8 ni frags + t-quad lanes
        #pragma unroll
        for (int rs = 0; rs < 2; rs++) {
            float mx = -1e30f;
            #pragma unroll
            for (int ni = 0; ni < 8; ni++)
                mx = fmaxf(mx, fmaxf(s[ni][rs*2], s[ni][rs*2+1]));
            mx = fmaxf(mx, __shfl_xor_sync(0xffffffffu, mx, 1));
            mx = fmaxf(mx, __shfl_xor_sync(0xffffffffu, mx, 2));
            float mnew = fmaxf(m_[rs], mx);
            float corr = __expf(m_[rs] - mnew);
            float ps = 0.f;
            #pragma unroll
            for (int ni = 0; ni < 8; ni++) {
                float p0 = __expf(s[ni][rs*2]     - mnew);
                float p1 = __expf(s[ni][rs*2 + 1] - mnew);
                s[ni][rs*2] = p0; s[ni][rs*2+1] = p1;
                ps += p0 + p1;
            }
            ps += __shfl_xor_sync(0xffffffffu, ps, 1);
            ps += __shfl_xor_sync(0xffffffffu, ps, 2);
            l_[rs] = l_[rs] * corr + ps;
            m_[rs] = mnew;
            #pragma unroll
            for (int ni = 0; ni < 8; ni++) {
                acc_o[ni][rs*2]   *= corr;
                acc_o[ni][rs*2+1] *= corr;
            }
        }

        // write P to warp-private smem rows (same-warp read below; no barrier needed)
        {
            int r0 = wm + g;
            #pragma unroll
            for (int ni = 0; ni < 8; ni++) {
                int c0 = ni * 8 + 2 * t;
                *reinterpret_cast<float2*>(Ps +  r0      * APAD + c0) = make_float2(s[ni][0], s[ni][1]);
                *reinterpret_cast<float2*>(Ps + (r0 + 8) * APAD + c0) = make_float2(s[ni][2], s[ni][3]);
            }
        }

        // O += P @ V  (A = own P rows, B = Vt shared)
        #pragma unroll
        for (int k8 = 0; k8 < 64; k8 += 8) {
            unsigned a[4];
            int r = wm + g;
            a[0] = f2tf(Ps[ r      * APAD + k8 + t]);
            a[1] = f2tf(Ps[(r + 8) * APAD + k8 + t]);
            a[2] = f2tf(Ps[ r      * APAD + k8 + t + 4]);
            a[3] = f2tf(Ps[(r + 8) * APAD + k8 + t + 4]);
            #pragma unroll
            for (int ni = 0; ni < 8; ni++) {
                int c = ni * 8 + g;
                unsigned b0 = f2tf(Vt[c * APAD + k8 + t]);
                unsigned b1 = f2tf(Vt[c * APAD + k8 + t + 4]);
                asm volatile(
                    "mma.sync.aligned.m16n8k8.row.col.f32.tf32.tf32.f32 "
                    "{%0,%1,%2,%3},{%4,%5,%6,%7},{%8,%9},{%0,%1,%2,%3};"
                    : "+f"(acc_o[ni][0]), "+f"(acc_o[ni][1]),
                      "+f"(acc_o[ni][2]), "+f"(acc_o[ni][3])
                    : "r"(a[0]), "r"(a[1]), "r"(a[2]), "r"(a[3]), "r"(b0), "r"(b1));
            }
        }
        __syncthreads();   // protect Ks/Vt before next tile's loads
    }

    // epilogue: divide by l, write ctx in (b, s, h, d)
    #pragma unroll
    for (int rs = 0; rs < 2; rs++) {
        float inv = 1.f / l_[rs];
        int r = qt * 128 + wm + rs * 8 + g;
        #pragma unroll
        for (int ni = 0; ni < 8; ni++) {
            int c = ni * 8 + 2 * t;
            float2 o2 = make_float2(acc_o[ni][rs*2] * inv, acc_o[ni][rs*2+1] * inv);
            *reinterpret_cast<float2*>(ctx + (size_t)(b * SEQ + r) * HID + h * HD + c) = o2;
        }
    }
}

// ---------------- driver ----------------
extern "C" void kernel_launch(void* const* d_in, const int* in_sizes, int n_in,
                              void* d_out, int out_size)
{
    const float* hidden  = (const float*)d_in[0];
    // d_in[1] = attention_mask (causal; applied analytically)
    const float* wq      = (const float*)d_in[2];
    const float* wk      = (const float*)d_in[3];
    const float* wv      = (const float*)d_in[4];
    const float* wo      = (const float*)d_in[5];
    const float* norm1w  = (const float*)d_in[6];
    const float* norm2w  = (const float*)d_in[7];
    const float* wgate   = (const float*)d_in[8];
    const float* wup     = (const float*)d_in[9];
    const float* wdown   = (const float*)d_in[10];
    const int*   posids  = (const int*)d_in[11];
    float* out = (float*)d_out;

    float *normed, *q, *k, *v, *ctx, *attn, *normed2, *g, *u, *rope;
    cudaGetSymbolAddress((void**)&normed,  d_normed);
    cudaGetSymbolAddress((void**)&q,       d_q);
    cudaGetSymbolAddress((void**)&k,       d_k);
    cudaGetSymbolAddress((void**)&v,       d_v);
    cudaGetSymbolAddress((void**)&ctx,     d_ctx);
    cudaGetSymbolAddress((void**)&attn,    d_attn);
    cudaGetSymbolAddress((void**)&normed2, d_normed2);
    cudaGetSymbolAddress((void**)&g,       d_g);
    cudaGetSymbolAddress((void**)&u,       d_u);
    cudaGetSymbolAddress((void**)&rope,    d_rope);

    cudaFuncSetAttribute(attn_mma, cudaFuncAttributeMaxDynamicSharedMemorySize, ATTM_SMEM);
    cudaFuncSetAttribute(gemm_tf32<0>, cudaFuncAttributeMaxDynamicSharedMemorySize, GEMM_SMEM);
    cudaFuncSetAttribute(gemm_tf32<1>, cudaFuncAttributeMaxDynamicSharedMemorySize, GEMM_SMEM);
    cudaFuncSetAttribute(gemm_tf32<2>, cudaFuncAttributeMaxDynamicSharedMemorySize, GEMM_SMEM);
    cudaFuncSetAttribute(qkv_kernel,   cudaFuncAttributeMaxDynamicSharedMemorySize, GEMM_SMEM);

    dim3 g2048(16, 16), g8192(64, 16);

    // 1) pre-attention norm
    rmsnorm_kernel<<<MROWS, 256>>>(hidden, nullptr, norm1w, normed);
    // 2) fused QKV projections
    qkv_kernel<<<dim3(24, 16), 256, GEMM_SMEM>>>(normed, wq, wk, wv, q, k, v);
    // 3) RoPE
    rope_table<<<(MROWS * 32) / 256, 256>>>(posids, rope);
    rope_apply<<<(MROWS * 40 * 32) / 256, 256>>>(q, k, rope);
    // 4) attention (tensor cores; 8 q-tiles of 128 rows x 64 bh)
    attn_mma<<<dim3(8, 64), 256, ATTM_SMEM>>>(q, k, v, ctx);
    // 5) output projection
    gemm_tf32<0><<<g2048, 256, GEMM_SMEM>>>(ctx, wo, attn, nullptr, HID, HID);
    // 6) post-attention norm (fused residual add)
    rmsnorm_kernel<<<MROWS, 256>>>(attn, hidden, norm2w, normed2);
    // 7) FFN: up, then gate with fused SwiGLU epilogue
    gemm_tf32<0><<<g8192, 256, GEMM_SMEM>>>(normed2, wup,   u, nullptr, FFND, HID);
    gemm_tf32<2><<<g8192, 256, GEMM_SMEM>>>(normed2, wgate, g, u,       FFND, HID);
    // 8) down projection + final residual (attn_out + ff)
    gemm_tf32<1><<<g2048, 256, GEMM_SMEM>>>(g, wdown, out, attn, HID, FFND);
}

// round 11
// speedup vs baseline: 1.0396x; 1.0396x over previous
#include <cuda_runtime.h>
#include <cstdint>
#include <math.h>

#define HID   2048
#define MROWS 2048      // b*s = 2*1024
#define SEQ   1024
#define NHEADS 32
#define NKV   8
#define HD    64
#define FFND  8192

// ---------------- scratch (static device arrays; no allocation) ----------------
__device__ float d_normed [MROWS * HID];
__device__ float d_q      [MROWS * HID];
__device__ float d_k      [MROWS * NKV * HD];
__device__ float d_v      [MROWS * NKV * HD];
__device__ float d_ctx    [MROWS * HID];
__device__ float d_attn   [MROWS * HID];
__device__ float d_normed2[MROWS * HID];
__device__ float d_g      [MROWS * FFND];
__device__ float d_u      [MROWS * FFND];
__device__ float d_rope   [MROWS * 64];       // per-row cos[32] | sin[32]

// ---------------- helpers ----------------
__device__ __forceinline__ unsigned f2tf(float x) {
    unsigned u;
    asm("cvt.rna.tf32.f32 %0, %1;" : "=r"(u) : "f"(x));
    return u;
}
__device__ __forceinline__ float rndtf(float x) { return __uint_as_float(f2tf(x)); }

// ---------------- RMSNorm (fused optional residual; output tf32-rounded: feeds GEMM A)
__global__ void __launch_bounds__(256) rmsnorm_kernel(
    const float* __restrict__ x, const float* __restrict__ res,
    const float* __restrict__ w, float* __restrict__ out)
{
    int row = blockIdx.x;
    int tid = threadIdx.x;
    const float4* xr = reinterpret_cast<const float4*>(x + (size_t)row * HID);
    float4 v0 = xr[tid];
    float4 v1 = xr[tid + 256];
    if (res) {
        const float4* rr = reinterpret_cast<const float4*>(res + (size_t)row * HID);
        float4 r0 = rr[tid], r1 = rr[tid + 256];
        v0.x += r0.x; v0.y += r0.y; v0.z += r0.z; v0.w += r0.w;
        v1.x += r1.x; v1.y += r1.y; v1.z += r1.z; v1.w += r1.w;
    }
    float ss = v0.x*v0.x + v0.y*v0.y + v0.z*v0.z + v0.w*v0.w
             + v1.x*v1.x + v1.y*v1.y + v1.z*v1.z + v1.w*v1.w;
    #pragma unroll
    for (int o = 16; o; o >>= 1) ss += __shfl_xor_sync(0xffffffffu, ss, o);
    __shared__ float red[8];
    if ((tid & 31) == 0) red[tid >> 5] = ss;
    __syncthreads();
    float tot = red[0] + red[1] + red[2] + red[3] + red[4] + red[5] + red[6] + red[7];
    float sc = rsqrtf(tot / (float)HID + 1e-5f);
    const float4* wr = reinterpret_cast<const float4*>(w);
    float4 w0 = wr[tid], w1 = wr[tid + 256];
    float4 o0 = make_float4(rndtf(v0.x*sc*w0.x), rndtf(v0.y*sc*w0.y),
                            rndtf(v0.z*sc*w0.z), rndtf(v0.w*sc*w0.w));
    float4 o1 = make_float4(rndtf(v1.x*sc*w1.x), rndtf(v1.y*sc*w1.y),
                            rndtf(v1.z*sc*w1.z), rndtf(v1.w*sc*w1.w));
    float4* orow = reinterpret_cast<float4*>(out + (size_t)row * HID);
    orow[tid]       = o0;
    orow[tid + 256] = o1;
}

// ---------------- tf32 GEMM core: 128x128 tile, BK=16, double-buffered cp.async -------
// A is pre-rounded to tf32 by producers -> A fragments load raw (no CVT).
// B (weights) converted in-kernel via f2tf.
// mode: 0 plain, 1 C = acc + Add, 3 C = silu(acc)  (raw; multiply+round happens later)
struct GemmSmem {
    float As[2][128][20];   // pad 16->20: frag banks (20g+t)%32 distinct
    float Bs[2][16][136];   // pad 128->136: frag banks (8t+g)%32 distinct
};

__device__ __forceinline__ void gemm_body(
    const float* __restrict__ A, const float* __restrict__ B,
    float* __restrict__ C, const float* __restrict__ Add,
    int N, int K, int bm, int bn, int mode, GemmSmem* gs)
{
    constexpr int BK = 16;
    int tid = threadIdx.x;
    int warp = tid >> 5, lane = tid & 31;
    int wm = (warp >> 2) * 64, wn = (warp & 3) * 32;
    int g = lane >> 2, t = lane & 3;

    int ar0 = tid >> 2, ac0 = (tid & 3) * 4;   // A: 16B chunk coords
    int br0 = tid >> 5, bc0 = (tid & 31) * 4;  // B: 16B chunk coords

    const float* aSrc = A + (size_t)(bm + ar0) * K + ac0;
    const float* bSrc = B + (size_t)br0 * N + bn + bc0;
    const size_t aStep = 64 * (size_t)K;
    const size_t bStep = 8 * (size_t)N;

    float acc[4][4][4] = {};
    int KT = K >> 4;

    auto issue = [&](int buf) {
        unsigned d0 = (unsigned)__cvta_generic_to_shared(&gs->As[buf][ar0][ac0]);
        asm volatile("cp.async.cg.shared.global [%0], [%1], 16;\n" :: "r"(d0), "l"(aSrc));
        unsigned d1 = (unsigned)__cvta_generic_to_shared(&gs->As[buf][ar0 + 64][ac0]);
        asm volatile("cp.async.cg.shared.global [%0], [%1], 16;\n" :: "r"(d1), "l"(aSrc + aStep));
        unsigned d2 = (unsigned)__cvta_generic_to_shared(&gs->Bs[buf][br0][bc0]);
        asm volatile("cp.async.cg.shared.global [%0], [%1], 16;\n" :: "r"(d2), "l"(bSrc));
        unsigned d3 = (unsigned)__cvta_generic_to_shared(&gs->Bs[buf][br0 + 8][bc0]);
        asm volatile("cp.async.cg.shared.global [%0], [%1], 16;\n" :: "r"(d3), "l"(bSrc + bStep));
        asm volatile("cp.async.commit_group;\n");
        aSrc += BK;
        bSrc += (size_t)BK * N;
    };

    issue(0);
    int cur = 0;
    for (int kt = 0; kt < KT; kt++) {
        if (kt + 1 < KT) {
            issue(cur ^ 1);
            asm volatile("cp.async.wait_group 1;\n");
        } else {
            asm volatile("cp.async.wait_group 0;\n");
        }
        __syncthreads();

        #pragma unroll
        for (int ks = 0; ks < BK; ks += 8) {
            unsigned a[4][4], b[4][2];
            #pragma unroll
            for (int mi = 0; mi < 4; mi++) {
                int r = wm + mi * 16 + g;
                a[mi][0] = __float_as_uint(gs->As[cur][r    ][ks + t]);
                a[mi][1] = __float_as_uint(gs->As[cur][r + 8][ks + t]);
                a[mi][2] = __float_as_uint(gs->As[cur][r    ][ks + t + 4]);
                a[mi][3] = __float_as_uint(gs->As[cur][r + 8][ks + t + 4]);
            }
            #pragma unroll
            for (int ni = 0; ni < 4; ni++) {
                int c = wn + ni * 8 + g;
                b[ni][0] = f2tf(gs->Bs[cur][ks + t    ][c]);
                b[ni][1] = f2tf(gs->Bs[cur][ks + t + 4][c]);
            }
            #pragma unroll
            for (int mi = 0; mi < 4; mi++)
                #pragma unroll
                for (int ni = 0; ni < 4; ni++) {
                    asm volatile(
                        "mma.sync.aligned.m16n8k8.row.col.f32.tf32.tf32.f32 "
                        "{%0,%1,%2,%3},{%4,%5,%6,%7},{%8,%9},{%0,%1,%2,%3};"
                        : "+f"(acc[mi][ni][0]), "+f"(acc[mi][ni][1]),
                          "+f"(acc[mi][ni][2]), "+f"(acc[mi][ni][3])
                        : "r"(a[mi][0]), "r"(a[mi][1]), "r"(a[mi][2]), "r"(a[mi][3]),
                          "r"(b[ni][0]), "r"(b[ni][1]));
                }
        }
        __syncthreads();
        cur ^= 1;
    }

    // epilogue (float2 stores)
    #pragma unroll
    for (int mi = 0; mi < 4; mi++) {
        #pragma unroll
        for (int ni = 0; ni < 4; ni++) {
            int r0 = bm + wm + mi * 16 + g;
            int c0 = bn + wn + ni * 8 + 2 * t;
            size_t i0 = (size_t)r0 * N + c0;
            size_t i1 = i0 + (size_t)8 * N;
            float2 lo = make_float2(acc[mi][ni][0], acc[mi][ni][1]);
            float2 hi = make_float2(acc[mi][ni][2], acc[mi][ni][3]);
            if (mode == 1) {
                const float2 a0 = *reinterpret_cast<const float2*>(Add + i0);
                const float2 a1 = *reinterpret_cast<const float2*>(Add + i1);
                lo.x += a0.x; lo.y += a0.y; hi.x += a1.x; hi.y += a1.y;
            } else if (mode == 3) {
                lo.x = lo.x / (1.f + __expf(-lo.x));
                lo.y = lo.y / (1.f + __expf(-lo.y));
                hi.x = hi.x / (1.f + __expf(-hi.x));
                hi.y = hi.y / (1.f + __expf(-hi.y));
            }
            *reinterpret_cast<float2*>(C + i0) = lo;
            *reinterpret_cast<float2*>(C + i1) = hi;
        }
    }
}

__global__ void __launch_bounds__(256, 2) gemm_tf32(
    const float* __restrict__ A, const float* __restrict__ B,
    float* __restrict__ C, const float* __restrict__ Add,
    int N, int K, int mode)
{
    __shared__ GemmSmem gs;
    gemm_body(A, B, C, Add, N, K, blockIdx.y * 128, blockIdx.x * 128, mode, &gs);
}

// fused QKV: grid (24, 16); tiles 0-15 -> Q, 16-19 -> K, 20-23 -> V
__global__ void __launch_bounds__(256, 2) qkv_kernel(
    const float* __restrict__ A,
    const float* __restrict__ wq, const float* __restrict__ wk, const float* __restrict__ wv,
    float* __restrict__ q, float* __restrict__ k, float* __restrict__ v)
{
    __shared__ GemmSmem gs;
    int nt = blockIdx.x, bm = blockIdx.y * 128;
    const float* B; float* Cp; int N, bn;
    if (nt < 16)      { B = wq; Cp = q; N = HID;      bn = nt * 128; }
    else if (nt < 20) { B = wk; Cp = k; N = NKV * HD; bn = (nt - 16) * 128; }
    else              { B = wv; Cp = v; N = NKV * HD; bn = (nt - 20) * 128; }
    gemm_body(A, B, Cp, nullptr, N, HID, bm, bn, 0, &gs);
}

// fused up+gate: grid (128, 16); tiles 0-63 -> up (plain), 64-127 -> gate (silu).
// Removes the up->gate dependency so both pack into ONE 2048-CTA launch (7 waves vs 8).
__global__ void __launch_bounds__(256, 2) upgate_kernel(
    const float* __restrict__ A,
    const float* __restrict__ wup, const float* __restrict__ wgate,
    float* __restrict__ u, float* __restrict__ g)
{
    __shared__ GemmSmem gs;
    int nt = blockIdx.x, bm = blockIdx.y * 128;
    const float* B; float* Cp; int bn, mode;
    if (nt < 64) { B = wup;   Cp = u; bn = nt * 128;        mode = 0; }
    else         { B = wgate; Cp = g; bn = (nt - 64) * 128; mode = 3; }
    gemm_body(A, B, Cp, nullptr, FFND, HID, bm, bn, mode, &gs);
}

// g = tf32_round(silu_g * u)   (g already holds silu(gate))
__global__ void __launch_bounds__(256) swiglu_mul(
    float* __restrict__ g, const float* __restrict__ u, int n4)
{
    int i = blockIdx.x * 256 + threadIdx.x;
    if (i < n4) {
        float4 gv = reinterpret_cast<float4*>(g)[i];
        float4 uv = reinterpret_cast<const float4*>(u)[i];
        gv.x = rndtf(gv.x * uv.x);
        gv.y = rndtf(gv.y * uv.y);
        gv.z = rndtf(gv.z * uv.z);
        gv.w = rndtf(gv.w * uv.w);
        reinterpret_cast<float4*>(g)[i] = gv;
    }
}

// ---------------- RoPE ----------------
__global__ void __launch_bounds__(256) rope_table(
    const int* __restrict__ pos, float* __restrict__ tab)
{
    int idx = blockIdx.x * 256 + threadIdx.x;   // MROWS*32
    int row = idx >> 5, i = idx & 31;
    double invf = exp2(-(double)i * (18.931568569324174 / 32.0)); // 500000^{-i/32}
    float ang = (float)((double)pos[row] * invf);
    float s, c;
    sincosf(ang, &s, &c);
    tab[row * 64 + i]      = c;
    tab[row * 64 + 32 + i] = s;
}

__global__ void __launch_bounds__(256) rope_apply(
    float* __restrict__ q, float* __restrict__ k, const float* __restrict__ tab)
{
    int id = blockIdx.x * 256 + threadIdx.x;    // MROWS * 40 * 32
    int row = id / (40 * 32);
    int rem = id - row * (40 * 32);
    int head = rem >> 5;
    int i = rem & 31;
    float c = tab[row * 64 + i], s = tab[row * 64 + 32 + i];
    float* base;
    if (head < NHEADS) base = q + (size_t)row * HID + head * HD;
    else               base = k + (size_t)row * (NKV * HD) + (head - NHEADS) * HD;
    float x1 = base[i], x2 = base[i + 32];
    base[i]      = x1 * c - x2 * s;
    base[i + 32] = x2 * c + x1 * s;
}

// ---------------- tensor-core flash attention (tf32 mma.sync, causal, GQA) -----------
// Operands tf32-rounded AT SMEM STORE (once/element) -> fragment loads are raw (no CVT).
// qt reversed so the long triangular blocks launch first.
#define APAD 68
#define ATTM_SMEM ((128 + 64 + 128 + 64) * APAD * 4)
__global__ void __launch_bounds__(256) attn_mma(
    const float* __restrict__ q, const float* __restrict__ kk,
    const float* __restrict__ vv, float* __restrict__ ctx)
{
    extern __shared__ float sm[];
    float* Qs = sm;                   // [128][APAD] q rows (pre-scaled by 1/8, rounded)
    float* Ks = Qs + 128 * APAD;      // [64][APAD]  key rows (rounded)
    float* Ps = Ks + 64 * APAD;       // [128][APAD] probabilities (rounded, warp-private)
    float* Vt = Ps + 128 * APAD;      // [64][APAD]  V transposed (rounded)

    int qt = 7 - blockIdx.x;          // long blocks first
    int bh = blockIdx.y;
    int b = bh >> 5, h = bh & 31, kvh = h >> 2;
    const float* qb = q  + ((size_t)b * SEQ + qt * 128) * HID + h * HD;
    const float* kb = kk + (size_t)b * SEQ * (NKV * HD) + kvh * HD;
    const float* vb = vv + (size_t)b * SEQ * (NKV * HD) + kvh * HD;

    int tid = threadIdx.x, warp = tid >> 5, lane = tid & 31;
    int wm = warp * 16;
    int g = lane >> 2, t = lane & 3;

    // load Q tile (128x64), scale 1/8 then round
    #pragma unroll
    for (int i = 0; i < 8; i++) {
        int idx = tid + i * 256;
        int r = idx >> 4, c4 = idx & 15;
        float4 val = *reinterpret_cast<const float4*>(qb + (size_t)r * HID + c4 * 4);
        val.x = rndtf(val.x * 0.125f); val.y = rndtf(val.y * 0.125f);
        val.z = rndtf(val.z * 0.125f); val.w = rndtf(val.w * 0.125f);
        *reinterpret_cast<float4*>(Qs + r * APAD + c4 * 4) = val;
    }

    float acc_o[8][4] = {};
    float m_[2] = {-1e30f, -1e30f};
    float l_[2] = {0.f, 0.f};

    int ktmax = 2 * qt + 1;
    for (int kt = 0; kt <= ktmax; kt++) {
        // load K rows + V transposed (64x64 each), rounded at store
        #pragma unroll
        for (int i = 0; i < 4; i++) {
            int idx = tid + i * 256;
            int r = idx >> 4, c4 = idx & 15;
            float4 kval = *reinterpret_cast<const float4*>(kb + (size_t)(kt * 64 + r) * (NKV * HD) + c4 * 4);
            kval.x = rndtf(kval.x); kval.y = rndtf(kval.y);
            kval.z = rndtf(kval.z); kval.w = rndtf(kval.w);
            *reinterpret_cast<float4*>(Ks + r * APAD + c4 * 4) = kval;
            float4 vval = *reinterpret_cast<const float4*>(vb + (size_t)(kt * 64 + r) * (NKV * HD) + c4 * 4);
            Vt[(c4 * 4 + 0) * APAD + r] = rndtf(vval.x);
            Vt[(c4 * 4 + 1) * APAD + r] = rndtf(vval.y);
            Vt[(c4 * 4 + 2) * APAD + r] = rndtf(vval.z);
            Vt[(c4 * 4 + 3) * APAD + r] = rndtf(vval.w);
        }
        __syncthreads();

        // S = Qs @ K^T  (raw fragment loads; data already tf32)
        float s[8][4] = {};
        #pragma unroll
        for (int k8 = 0; k8 < 64; k8 += 8) {
            unsigned a[4];
            int r = wm + g;
            a[0] = __float_as_uint(Qs[ r      * APAD + k8 + t]);
            a[1] = __float_as_uint(Qs[(r + 8) * APAD + k8 + t]);
            a[2] = __float_as_uint(Qs[ r      * APAD + k8 + t + 4]);
            a[3] = __float_as_uint(Qs[(r + 8) * APAD + k8 + t + 4]);
            #pragma unroll
            for (int ni = 0; ni < 8; ni++) {
                int c = ni * 8 + g;
                unsigned b0 = __float_as_uint(Ks[c * APAD + k8 + t]);
                unsigned b1 = __float_as_uint(Ks[c * APAD + k8 + t + 4]);
                asm volatile(
                    "mma.sync.aligned.m16n8k8.row.col.f32.tf32.tf32.f32 "
                    "{%0,%1,%2,%3},{%4,%5,%6,%7},{%8,%9},{%0,%1,%2,%3};"
                    : "+f"(s[ni][0]), "+f"(s[ni][1]), "+f"(s[ni][2]), "+f"(s[ni][3])
                    : "r"(a[0]), "r"(a[1]), "r"(a[2]), "r"(a[3]), "r"(b0), "r"(b1));
            }
        }

        // causal mask (only the two diagonal-straddling key tiles can mask)
        if (kt >= 2 * qt) {
            int R0 = qt * 128 + wm + g, R1 = R0 + 8;
            #pragma unroll
            for (int ni = 0; ni < 8; ni++) {
                int c0 = kt * 64 + ni * 8 + 2 * t;
                if (c0     > R0) s[ni][0] = -1e30f;
                if (c0 + 1 > R0) s[ni][1] = -1e30f;
                if (c0     > R1) s[ni][2] = -1e30f;
                if (c0 + 1 > R1) s[ni][3] = -1e30f;
            }
        }

        // online softmax: rows warp-owned; reduce over 8 ni frags + t-quad lanes
        #pragma unroll
        for (int rs = 0; rs < 2; rs++) {
            float mx = -1e30f;
            #pragma unroll
            for (int ni = 0; ni < 8; ni++)
                mx = fmaxf(mx, fmaxf(s[ni][rs*2], s[ni][rs*2+1]));
            mx = fmaxf(mx, __shfl_xor_sync(0xffffffffu, mx, 1));
            mx = fmaxf(mx, __shfl_xor_sync(0xffffffffu, mx, 2));
            float mnew = fmaxf(m_[rs], mx);
            float corr = __expf(m_[rs] - mnew);
            float ps = 0.f;
            #pragma unroll
            for (int ni = 0; ni < 8; ni++) {
                float p0 = __expf(s[ni][rs*2]     - mnew);
                float p1 = __expf(s[ni][rs*2 + 1] - mnew);
                s[ni][rs*2] = p0; s[ni][rs*2+1] = p1;
                ps += p0 + p1;
            }
            ps += __shfl_xor_sync(0xffffffffu, ps, 1);
            ps += __shfl_xor_sync(0xffffffffu, ps, 2);
            l_[rs] = l_[rs] * corr + ps;
            m_[rs] = mnew;
            #pragma unroll
            for (int ni = 0; ni < 8; ni++) {
                acc_o[ni][rs*2]   *= corr;
                acc_o[ni][rs*2+1] *= corr;
            }
        }

        // write P (rounded) to warp-private smem rows
        {
            int r0 = wm + g;
            #pragma unroll
            for (int ni = 0; ni < 8; ni++) {
                int c0 = ni * 8 + 2 * t;
                *reinterpret_cast<float2*>(Ps +  r0      * APAD + c0) =
                    make_float2(rndtf(s[ni][0]), rndtf(s[ni][1]));
                *reinterpret_cast<float2*>(Ps + (r0 + 8) * APAD + c0) =
                    make_float2(rndtf(s[ni][2]), rndtf(s[ni][3]));
            }
        }

        // O += P @ V  (raw fragment loads)
        #pragma unroll
        for (int k8 = 0; k8 < 64; k8 += 8) {
            unsigned a[4];
            int r = wm + g;
            a[0] = __float_as_uint(Ps[ r      * APAD + k8 + t]);
            a[1] = __float_as_uint(Ps[(r + 8) * APAD + k8 + t]);
            a[2] = __float_as_uint(Ps[ r      * APAD + k8 + t + 4]);
            a[3] = __float_as_uint(Ps[(r + 8) * APAD + k8 + t + 4]);
            #pragma unroll
            for (int ni = 0; ni < 8; ni++) {
                int c = ni * 8 + g;
                unsigned b0 = __float_as_uint(Vt[c * APAD + k8 + t]);
                unsigned b1 = __float_as_uint(Vt[c * APAD + k8 + t + 4]);
                asm volatile(
                    "mma.sync.aligned.m16n8k8.row.col.f32.tf32.tf32.f32 "
                    "{%0,%1,%2,%3},{%4,%5,%6,%7},{%8,%9},{%0,%1,%2,%3};"
                    : "+f"(acc_o[ni][0]), "+f"(acc_o[ni][1]),
                      "+f"(acc_o[ni][2]), "+f"(acc_o[ni][3])
                    : "r"(a[0]), "r"(a[1]), "r"(a[2]), "r"(a[3]), "r"(b0), "r"(b1));
            }
        }
        __syncthreads();   // protect Ks/Vt before next tile's loads
    }

    // epilogue: divide by l, round (ctx feeds WO GEMM A operand), write (b, s, h, d)
    #pragma unroll
    for (int rs = 0; rs < 2; rs++) {
        float inv = 1.f / l_[rs];
        int r = qt * 128 + wm + rs * 8 + g;
        #pragma unroll
        for (int ni = 0; ni < 8; ni++) {
            int c = ni * 8 + 2 * t;
            float2 o2 = make_float2(rndtf(acc_o[ni][rs*2] * inv),
                                    rndtf(acc_o[ni][rs*2+1] * inv));
            *reinterpret_cast<float2*>(ctx + (size_t)(b * SEQ + r) * HID + h * HD + c) = o2;
        }
    }
}

// ---------------- driver ----------------
extern "C" void kernel_launch(void* const* d_in, const int* in_sizes, int n_in,
                              void* d_out, int out_size)
{
    const float* hidden  = (const float*)d_in[0];
    // d_in[1] = attention_mask (causal; applied analytically)
    const float* wq      = (const float*)d_in[2];
    const float* wk      = (const float*)d_in[3];
    const float* wv      = (const float*)d_in[4];
    const float* wo      = (const float*)d_in[5];
    const float* norm1w  = (const float*)d_in[6];
    const float* norm2w  = (const float*)d_in[7];
    const float* wgate   = (const float*)d_in[8];
    const float* wup     = (const float*)d_in[9];
    const float* wdown   = (const float*)d_in[10];
    const int*   posids  = (const int*)d_in[11];
    float* out = (float*)d_out;

    float *normed, *q, *k, *v, *ctx, *attn, *normed2, *g, *u, *rope;
    cudaGetSymbolAddress((void**)&normed,  d_normed);
    cudaGetSymbolAddress((void**)&q,       d_q);
    cudaGetSymbolAddress((void**)&k,       d_k);
    cudaGetSymbolAddress((void**)&v,       d_v);
    cudaGetSymbolAddress((void**)&ctx,     d_ctx);
    cudaGetSymbolAddress((void**)&attn,    d_attn);
    cudaGetSymbolAddress((void**)&normed2, d_normed2);
    cudaGetSymbolAddress((void**)&g,       d_g);
    cudaGetSymbolAddress((void**)&u,       d_u);
    cudaGetSymbolAddress((void**)&rope,    d_rope);

    cudaFuncSetAttribute(attn_mma, cudaFuncAttributeMaxDynamicSharedMemorySize, ATTM_SMEM);

    // 1) pre-attention norm (tf32-rounded output)
    rmsnorm_kernel<<<MROWS, 256>>>(hidden, nullptr, norm1w, normed);
    // 2) fused QKV projections
    qkv_kernel<<<dim3(24, 16), 256>>>(normed, wq, wk, wv, q, k, v);
    // 3) RoPE
    rope_table<<<(MROWS * 32) / 256, 256>>>(posids, rope);
    rope_apply<<<(MROWS * 40 * 32) / 256, 256>>>(q, k, rope);
    // 4) attention (tensor cores; long blocks first)
    attn_mma<<<dim3(8, 64), 256, ATTM_SMEM>>>(q, k, v, ctx);
    // 5) output projection
    gemm_tf32<<<dim3(16, 16), 256>>>(ctx, wo, attn, nullptr, HID, HID, 0);
    // 6) post-attention norm (fused residual add, rounded)
    rmsnorm_kernel<<<MROWS, 256>>>(attn, hidden, norm2w, normed2);
    // 7) FFN: up + gate in ONE launch (gate writes raw silu), then multiply+round
    upgate_kernel<<<dim3(128, 16), 256>>>(normed2, wup, wgate, u, g);
    swiglu_mul<<<(MROWS * FFND / 4 + 255) / 256, 256>>>(g, u, MROWS * FFND / 4);
    // 8) down projection + final residual (attn_out + ff)
    gemm_tf32<<<dim3(16, 16), 256>>>(g, wdown, out, attn, HID, FFND, 1);
}